// round 13
// baseline (speedup 1.0000x reference)
#include <cuda_runtime.h>
#include <cstdint>

// Problem constants
#define NB  4
#define NT  1024
#define ND  1024
#define NH  16
#define NHD 64

// ---------------------------------------------------------------------------
// Scratch (alloc-free: __device__ globals)
// ---------------------------------------------------------------------------
static __device__ float g_K  [(size_t)NB * NT * ND];           // 16 MB
static __device__ float g_Q  [(size_t)NB * NT * ND];           // 16 MB
static __device__ float g_V  [(size_t)NB * NT * ND];           // 16 MB
static __device__ float g_AO [(size_t)NB * NT * ND];           // 16 MB (tf32-rounded, PERMUTED octets)
static __device__ float g_S  [(size_t)NB * NH * NT * NT];      // 256 MB  [b,h,k,q] raw scores
static __device__ float g_stM[(size_t)NB * NH * NT];           // per-row max
static __device__ float g_stI[(size_t)NB * NH * NT];           // per-row 1/sum
static __device__ float g_X  [(size_t)NB * NT * ND];           // 16 MB  rna(x), PERMUTED octets
static __device__ float g_W4 [(size_t)4  * ND * ND];           // 16 MB  rna(W*), PERMUTED octets

// Octet permutation: element k sits at position (k&3)*2 + ((k>>2)&1) within
// its 8-wide k-group. Then the mma fragment pair (k=tg, k=tg+4) is one float2.

// ---------------------------------------------------------------------------
// tf32 / mma helpers
// ---------------------------------------------------------------------------
__device__ __forceinline__ uint32_t f2tf32(float v) {
    uint32_t u;
    asm("cvt.rna.tf32.f32 %0, %1;" : "=r"(u) : "f"(v));
    return u;
}
__device__ __forceinline__ float f2tf32f(float v) { return __uint_as_float(f2tf32(v)); }

__device__ __forceinline__ void mma_tf32(float& c0, float& c1, float& c2, float& c3,
                                         uint32_t a0, uint32_t a1, uint32_t a2, uint32_t a3,
                                         uint32_t b0, uint32_t b1) {
    asm volatile(
        "mma.sync.aligned.m16n8k8.row.col.f32.tf32.tf32.f32 "
        "{%0,%1,%2,%3}, {%4,%5,%6,%7}, {%8,%9}, {%0,%1,%2,%3};"
        : "+f"(c0), "+f"(c1), "+f"(c2), "+f"(c3)
        : "r"(a0), "r"(a1), "r"(a2), "r"(a3), "r"(b0), "r"(b1));
}

// ---------------------------------------------------------------------------
// cp.async helpers
// ---------------------------------------------------------------------------
__device__ __forceinline__ void cp_async16(uint32_t dst, const void* src) {
    asm volatile("cp.async.cg.shared.global [%0], [%1], 16;" :: "r"(dst), "l"(src));
}
__device__ __forceinline__ void cp_commit() {
    asm volatile("cp.async.commit_group;" ::: "memory");
}
__device__ __forceinline__ void cp_wait1() {
    asm volatile("cp.async.wait_group 1;" ::: "memory");
}

// ---------------------------------------------------------------------------
// Pre-round + permute pass: for x and the 4 weight matrices,
//   dst[row][oct + perm(k)] = rna_tf32(src[row][k])
// grid.z: 0 = x (1M float4), 1..4 = Wk,Wq,Wv,Wp (256K float4 each).
// ---------------------------------------------------------------------------
__global__ __launch_bounds__(256) void preround_k(
    const float* __restrict__ x,
    const float* __restrict__ Wk, const float* __restrict__ Wq,
    const float* __restrict__ Wv, const float* __restrict__ Wp)
{
    const int z = blockIdx.z;
    const float* src; float* dst; int n4;
    if (z == 0) { src = x;  dst = g_X;               n4 = (NB * NT * ND) / 4; }
    else {
        const float* Ws[4] = {Wk, Wq, Wv, Wp};
        src = Ws[z - 1]; dst = g_W4 + (size_t)(z - 1) * ND * ND; n4 = (ND * ND) / 4;
    }
    const int i = blockIdx.x * 256 + threadIdx.x;
    if (i < n4) {
        float4 v = ((const float4*)src)[i];
        const int e0  = i * 4;                 // linear index of v.x
        const int oct = e0 & ~7;               // octet base (e0 % 8 is 0 or 4)
        const int par = (e0 >> 2) & 1;         // 0 for k%8<4, 1 otherwise
        float* d = dst + oct + par;
        d[0] = f2tf32f(v.x);
        d[2] = f2tf32f(v.y);
        d[4] = f2tf32f(v.z);
        d[6] = f2tf32f(v.w);
    }
}

// ---------------------------------------------------------------------------
// Async-pipelined tf32 GEMM body: C[m,n] = sum_k A[m,k]*W[n,k] + bias[n]
// Inputs MUST be pre-rounded AND octet-permuted. 128x128 block, K-step 16,
// 3-stage cp.async pipeline. SMEM row stride 20 words. Fragment gathers are
// float2 (LDS.64) thanks to the permuted layout. 8 warps, warp tile 32x64.
// Epilogue writes NORMAL (un-permuted) layout.
// dynamic smem: 6 * 128 * 20 * 4 = 61440 bytes
// ---------------------------------------------------------------------------
#define PSTG 2560              // floats per stage per matrix (128*20)

__device__ __forceinline__ void gemm_async_body(
    const float* __restrict__ A,
    const float* __restrict__ W,
    const float* __restrict__ bias,
    float* __restrict__ C,
    float* smem)
{
    const int m0 = blockIdx.y * 128, n0 = blockIdx.x * 128;
    const int tid  = threadIdx.x;
    const int wid  = tid >> 5, lane = tid & 31;
    const int gid  = lane >> 2, tg = lane & 3;
    const int wr   = (wid & 3) * 32;
    const int wc   = (wid >> 2) * 64;

    const int lrow = tid >> 2;          // 0..63
    const int lcol = (tid & 3) * 4;     // 0,4,8,12

    const float* Ag0 = A + (size_t)(m0 + lrow) * ND + lcol;
    const float* Ag1 = Ag0 + (size_t)64 * ND;
    const float* Wg0 = W + (size_t)(n0 + lrow) * ND + lcol;
    const float* Wg1 = Wg0 + (size_t)64 * ND;

    const uint32_t sbase = (uint32_t)__cvta_generic_to_shared(smem);
    const uint32_t loff  = (uint32_t)(lrow * 20 + lcol) * 4;
    const uint32_t rstep = 64 * 20 * 4;

    float acc[2][8][4] = {};

    #define ISSUE(k0_, s_)                                                     \
    {                                                                          \
        const uint32_t sa = sbase + (uint32_t)(s_) * PSTG * 4 + loff;          \
        const uint32_t sb = sa + 3 * PSTG * 4;                                 \
        cp_async16(sa,         Ag0 + (k0_));                                   \
        cp_async16(sa + rstep, Ag1 + (k0_));                                   \
        cp_async16(sb,         Wg0 + (k0_));                                   \
        cp_async16(sb + rstep, Wg1 + (k0_));                                   \
    }

    // prologue: stages 0,1
    ISSUE(0, 0)  cp_commit();
    ISSUE(16, 1) cp_commit();

    int slot = 0;
    for (int k0 = 0; k0 < ND; k0 += 16) {
        cp_wait1();
        __syncthreads();

        // issue k0+32 into the slot that held k0-16 (finished last iteration)
        if (k0 + 32 < ND) {
            const int ns = (slot + 2 >= 3) ? slot - 1 : slot + 2;
            ISSUE(k0 + 32, ns)
        }
        cp_commit();

        const float* sAp = smem + slot * PSTG;
        const float* sBp = sAp + 3 * PSTG;

        #pragma unroll
        for (int oct = 0; oct < 2; oct++) {
            const int kc = oct * 8 + 2 * tg;          // permuted pair (tg, tg+4)
            uint32_t af[2][4], bf[8][2];
            #pragma unroll
            for (int mi = 0; mi < 2; mi++) {
                const int r = wr + mi * 16 + gid;
                float2 f0 = *(const float2*)&sAp[(r    ) * 20 + kc];
                float2 f1 = *(const float2*)&sAp[(r + 8) * 20 + kc];
                af[mi][0] = __float_as_uint(f0.x); af[mi][2] = __float_as_uint(f0.y);
                af[mi][1] = __float_as_uint(f1.x); af[mi][3] = __float_as_uint(f1.y);
            }
            #pragma unroll
            for (int nj = 0; nj < 8; nj++) {
                const int c = wc + nj * 8 + gid;
                float2 fb = *(const float2*)&sBp[c * 20 + kc];
                bf[nj][0] = __float_as_uint(fb.x); bf[nj][1] = __float_as_uint(fb.y);
            }
            #pragma unroll
            for (int mi = 0; mi < 2; mi++)
                #pragma unroll
                for (int nj = 0; nj < 8; nj++)
                    mma_tf32(acc[mi][nj][0], acc[mi][nj][1], acc[mi][nj][2], acc[mi][nj][3],
                             af[mi][0], af[mi][1], af[mi][2], af[mi][3],
                             bf[nj][0], bf[nj][1]);
        }

        slot = (slot == 2) ? 0 : slot + 1;
    }
    #undef ISSUE

    #pragma unroll
    for (int mi = 0; mi < 2; mi++) {
        #pragma unroll
        for (int nj = 0; nj < 8; nj++) {
            const int gn = n0 + wc + nj * 8 + 2 * tg;
            const float b0v = bias[gn], b1v = bias[gn + 1];
            const int gm0 = m0 + wr + mi * 16 + gid;
            float2 v0; v0.x = acc[mi][nj][0] + b0v; v0.y = acc[mi][nj][1] + b1v;
            float2 v1; v1.x = acc[mi][nj][2] + b0v; v1.y = acc[mi][nj][3] + b1v;
            *(float2*)&C[(size_t)gm0 * ND + gn]       = v0;
            *(float2*)&C[(size_t)(gm0 + 8) * ND + gn] = v1;
        }
    }
}

// Fused QKV: grid.z selects which projection this block computes.
__global__ __launch_bounds__(256, 2) void qkv_async_k(
    const float* __restrict__ bk, const float* __restrict__ bq, const float* __restrict__ bv)
{
    extern __shared__ float smem[];
    const int z = blockIdx.z;
    const float* W = g_W4 + (size_t)z * ND * ND;
    const float* b = (z == 0) ? bk : (z == 1) ? bq : bv;
    float*       C = (z == 0) ? g_K : (z == 1) ? g_Q : g_V;
    gemm_async_body(g_X, W, b, C, smem);
}

__global__ __launch_bounds__(256, 2) void proj_async_k(
    const float* __restrict__ bias,
    float* __restrict__ C)
{
    extern __shared__ float smem[];
    gemm_async_body(g_AO, g_W4 + (size_t)3 * ND * ND, bias, C, smem);
}

// ---------------------------------------------------------------------------
// scores (tf32): scores[b,h,k,q] = (q>k) ? -1e30 : dot(K_row, Q_row) / 32
// 128x128 block per (b,h); K=64 staged once; permuted-k SMEM, stride 76.
// dynamic smem: 2 * 128 * 76 * 4 = 77824 B
// ---------------------------------------------------------------------------
__global__ __launch_bounds__(256, 2) void scores_tf32_k()
{
    extern __shared__ float sh[];
    float (*As)[76] = (float(*)[76])sh;                // [m][perm-k] K-rows
    float (*Bs)[76] = (float(*)[76])(sh + 128 * 76);   // [n][perm-k] Q-rows

    const int z = blockIdx.z, b = z >> 4, h = z & 15;
    const int m0 = blockIdx.y * 128, n0 = blockIdx.x * 128;  // m=k-idx, n=q-idx
    if (n0 > m0 + 127) return;                               // fully masked tile

    const float* __restrict__ A  = g_K + (size_t)b * NT * ND + h * NHD;
    const float* __restrict__ Bm = g_Q + (size_t)b * NT * ND + h * NHD;
    float* __restrict__ C = g_S + (size_t)z * NT * NT;

    const int tid = threadIdx.x;
    const int wid = tid >> 5, lane = tid & 31;
    const int gid = lane >> 2, tg = lane & 3;
    const int wr  = (wid & 3) * 32;
    const int wc  = (wid >> 2) * 64;

    // Stage full K=64 slab (permuted columns: pair (k, k+4) adjacent)
    #pragma unroll
    for (int i = 0; i < 8; i++) {
        const int idx = tid + i * 256;
        const int row = idx >> 4, c4 = (idx & 15) * 4;       // c4 in {0,4,...,60}
        const int pb  = (c4 & ~7) | ((c4 >> 2) & 1);         // octet base + parity
        float4 a4 = *(const float4*)&A [(size_t)(m0 + row) * ND + c4];
        float4 b4 = *(const float4*)&Bm[(size_t)(n0 + row) * ND + c4];
        As[row][pb+0] = f2tf32f(a4.x); As[row][pb+2] = f2tf32f(a4.y);
        As[row][pb+4] = f2tf32f(a4.z); As[row][pb+6] = f2tf32f(a4.w);
        Bs[row][pb+0] = f2tf32f(b4.x); Bs[row][pb+2] = f2tf32f(b4.y);
        Bs[row][pb+4] = f2tf32f(b4.z); Bs[row][pb+6] = f2tf32f(b4.w);
    }
    __syncthreads();

    float acc[2][8][4] = {};

    #pragma unroll
    for (int k0 = 0; k0 < NHD; k0 += 8) {
        const int kc = k0 + 2 * tg;
        uint32_t af[2][4], bf[8][2];
        #pragma unroll
        for (int mi = 0; mi < 2; mi++) {
            const int r = wr + mi * 16 + gid;
            float2 f0 = *(const float2*)&As[r    ][kc];
            float2 f1 = *(const float2*)&As[r + 8][kc];
            af[mi][0] = __float_as_uint(f0.x); af[mi][2] = __float_as_uint(f0.y);
            af[mi][1] = __float_as_uint(f1.x); af[mi][3] = __float_as_uint(f1.y);
        }
        #pragma unroll
        for (int nj = 0; nj < 8; nj++) {
            const int c = wc + nj * 8 + gid;
            float2 fb = *(const float2*)&Bs[c][kc];
            bf[nj][0] = __float_as_uint(fb.x); bf[nj][1] = __float_as_uint(fb.y);
        }
        #pragma unroll
        for (int mi = 0; mi < 2; mi++)
            #pragma unroll
            for (int nj = 0; nj < 8; nj++)
                mma_tf32(acc[mi][nj][0], acc[mi][nj][1], acc[mi][nj][2], acc[mi][nj][3],
                         af[mi][0], af[mi][1], af[mi][2], af[mi][3],
                         bf[nj][0], bf[nj][1]);
    }

    #pragma unroll
    for (int mi = 0; mi < 2; mi++) {
        #pragma unroll
        for (int nj = 0; nj < 8; nj++) {
            const int gn  = n0 + wc + nj * 8 + 2 * tg;
            const int gm0 = m0 + wr + mi * 16 + gid;
            float2 v0, v1;
            v0.x = (gn     > gm0)     ? -1e30f : acc[mi][nj][0] * 0.03125f;
            v0.y = (gn + 1 > gm0)     ? -1e30f : acc[mi][nj][1] * 0.03125f;
            v1.x = (gn     > gm0 + 8) ? -1e30f : acc[mi][nj][2] * 0.03125f;
            v1.y = (gn + 1 > gm0 + 8) ? -1e30f : acc[mi][nj][3] * 0.03125f;
            *(float2*)&C[(size_t)gm0 * NT + gn]       = v0;
            *(float2*)&C[(size_t)(gm0 + 8) * NT + gn] = v1;
        }
    }
}

// ---------------------------------------------------------------------------
// Stats + weights output for one (b,k) row-group (all 16 heads), 512 threads.
// SMEM row stride 1032 (16B-aligned rows -> STS.128 fill; 1032%32=8 keeps the
// reduction and the 4-head gather conflict-free).
// dynamic smem: 16 * 1032 * 4 = 66048 bytes
// ---------------------------------------------------------------------------
#define SHS 1032

__global__ __launch_bounds__(512) void stats_k(float* __restrict__ outW, int write_w)
{
    extern __shared__ float sh[];           // [16][SHS]
    __shared__ float s_inv[16];
    __shared__ float s_max[16];

    const int bk = blockIdx.x;
    const int b = bk >> 10, kidx = bk & 1023;
    const int tid = threadIdx.x;
    const size_t sbase = (size_t)b * NH * NT * NT + (size_t)kidx * NT;

    // fill sh with scores (float4 LDG + STS.128; -1e30 beyond kidx)
    for (int i = tid; i < (NH * NT) / 4; i += 512) {
        const int i4 = i * 4;
        const int h = i4 >> 10, q = i4 & 1023;
        float4 v;
        if (q + 3 <= kidx) {
            v = *(const float4*)&g_S[sbase + (size_t)h * NT * NT + q];
        } else if (q > kidx) {
            v.x = v.y = v.z = v.w = -1e30f;
        } else {
            const float* p = &g_S[sbase + (size_t)h * NT * NT + q];
            v.x = (q     <= kidx) ? p[0] : -1e30f;
            v.y = (q + 1 <= kidx) ? p[1] : -1e30f;
            v.z = (q + 2 <= kidx) ? p[2] : -1e30f;
            v.w = (q + 3 <= kidx) ? p[3] : -1e30f;
        }
        *(float4*)&sh[h * SHS + q] = v;
    }
    __syncthreads();

    const int warp = tid >> 5, lane = tid & 31;
    {
        const int h = warp;                 // 16 warps, one head each
        float m = -1e30f;
        for (int q = lane; q < NT; q += 32) m = fmaxf(m, sh[h * SHS + q]);
        #pragma unroll
        for (int o = 16; o; o >>= 1) m = fmaxf(m, __shfl_xor_sync(0xffffffffu, m, o));
        float s = 0.f;
        for (int q = lane; q < NT; q += 32) {
            const float e = __expf(sh[h * SHS + q] - m);
            sh[h * SHS + q] = e;
            s += e;
        }
        #pragma unroll
        for (int o = 16; o; o >>= 1) s += __shfl_xor_sync(0xffffffffu, s, o);
        if (lane == 0) { s_inv[h] = 1.0f / s; s_max[h] = m; }
    }
    __syncthreads();

    if (tid < NH) {
        g_stM[((size_t)b * NH + tid) * NT + kidx] = s_max[tid];
        g_stI[((size_t)b * NH + tid) * NT + kidx] = s_inv[tid];
    }

    if (write_w) {
        float* __restrict__ W = outW + (size_t)bk * NT * NH;
        for (int i = tid; i < (NT * NH) / 4; i += 512) {
            const int base = i * 4;
            const int q = base >> 4, h0 = base & 15;   // 4 consecutive heads, same q
            float4 v;
            if (q <= kidx) {
                v.x = sh[(h0+0) * SHS + q] * s_inv[h0+0];
                v.y = sh[(h0+1) * SHS + q] * s_inv[h0+1];
                v.z = sh[(h0+2) * SHS + q] * s_inv[h0+2];
                v.w = sh[(h0+3) * SHS + q] * s_inv[h0+3];
            } else {
                v.x = v.y = v.z = v.w = 0.f;
            }
            *(float4*)&W[base] = v;
        }
    }
}

// ---------------------------------------------------------------------------
// AV (tf32): AttnOut[b,k,h,:] = sum_q w[b,h,k,q] * V[b,q,h,:]
// Reads RAW scores, applies exp(v-m)*inv during SMEM fill, truncates to tf32.
// Epilogue stores rna_tf32(acc) in PERMUTED octet layout (input of proj).
// 128(M) x 64(N) block, K-step 32, K truncated at 128-aligned diagonal.
// ---------------------------------------------------------------------------
__global__ __launch_bounds__(256, 2) void av_tf32_k()
{
    __shared__ float As[128][36];   // [m][k] exp-weights (tf32 bits)
    __shared__ float Bs[64][36];    // [n][k] V^T (tf32 bits)
    __shared__ float rm[128], ri[128];

    const int z = blockIdx.z, b = z >> 4, h = z & 15;
    const int m0 = blockIdx.y * 128;
    const float* __restrict__ A  = g_S + (size_t)z * NT * NT;            // raw [k,q]
    const float* __restrict__ Bm = g_V + (size_t)b * NT * ND + h * NHD;  // [q,64] stride ND
    float* __restrict__ C = g_AO + (size_t)b * NT * ND + h * NHD;

    const int tid = threadIdx.x;
    const int wid = tid >> 5, lane = tid & 31;
    const int gid = lane >> 2, tg = lane & 3;
    const int wr  = wid * 16;

    if (tid < 128) {
        rm[tid] = g_stM[(size_t)z * NT + m0 + tid];
        ri[tid] = g_stI[(size_t)z * NT + m0 + tid];
    }
    __syncthreads();

    float acc[8][4] = {};

    const int Kend = m0 + 128;               // causal truncation (128-aligned)
    for (int k0 = 0; k0 < Kend; k0 += 32) {
        #pragma unroll
        for (int i = 0; i < 4; i++) {
            const int idx = tid + i * 256;
            const int row = idx >> 3, c4 = (idx & 7) * 4;
            float4 v = *(const float4*)&A[(size_t)(m0 + row) * NT + k0 + c4];
            const float m = rm[row], inv = ri[row];
            As[row][c4+0] = f2tf32f(__expf(v.x - m) * inv);
            As[row][c4+1] = f2tf32f(__expf(v.y - m) * inv);
            As[row][c4+2] = f2tf32f(__expf(v.z - m) * inv);
            As[row][c4+3] = f2tf32f(__expf(v.w - m) * inv);
        }
        #pragma unroll
        for (int i = 0; i < 2; i++) {
            const int idx = tid + i * 256;
            const int kk = idx >> 4, n4 = (idx & 15) * 4;
            float4 v = *(const float4*)&Bm[(size_t)(k0 + kk) * ND + n4];
            Bs[n4+0][kk] = f2tf32f(v.x);
            Bs[n4+1][kk] = f2tf32f(v.y);
            Bs[n4+2][kk] = f2tf32f(v.z);
            Bs[n4+3][kk] = f2tf32f(v.w);
        }
        __syncthreads();

        #pragma unroll
        for (int ks = 0; ks < 32; ks += 8) {
            uint32_t af[4], bf[8][2];
            const int r = wr + gid;
            af[0] = __float_as_uint(As[r    ][ks + tg]);
            af[1] = __float_as_uint(As[r + 8][ks + tg]);
            af[2] = __float_as_uint(As[r    ][ks + tg + 4]);
            af[3] = __float_as_uint(As[r + 8][ks + tg + 4]);
            #pragma unroll
            for (int nj = 0; nj < 8; nj++) {
                const int c = nj * 8 + gid;
                bf[nj][0] = __float_as_uint(Bs[c][ks + tg]);
                bf[nj][1] = __float_as_uint(Bs[c][ks + tg + 4]);
            }
            #pragma unroll
            for (int nj = 0; nj < 8; nj++)
                mma_tf32(acc[nj][0], acc[nj][1], acc[nj][2], acc[nj][3],
                         af[0], af[1], af[2], af[3], bf[nj][0], bf[nj][1]);
        }
        __syncthreads();
    }

    // store pre-rounded + octet-PERMUTED (exact-RNA, LDS.64-ready for proj).
    // Column k=2tg maps to p0, k=2tg+1 maps to p0+2 within the octet.
    const int p0 = ((2 * tg) & 3) * 2 + ((tg >> 1) & 1);
    #pragma unroll
    for (int nj = 0; nj < 8; nj++) {
        const int gm0 = m0 + wr + gid;
        float* r0 = &C[(size_t)gm0 * ND + nj * 8];
        float* r1 = &C[(size_t)(gm0 + 8) * ND + nj * 8];
        r0[p0]     = f2tf32f(acc[nj][0]);
        r0[p0 + 2] = f2tf32f(acc[nj][1]);
        r1[p0]     = f2tf32f(acc[nj][2]);
        r1[p0 + 2] = f2tf32f(acc[nj][3]);
    }
}

// ---------------------------------------------------------------------------
// Launch
// ---------------------------------------------------------------------------
extern "C" void kernel_launch(void* const* d_in, const int* in_sizes, int n_in,
                              void* d_out, int out_size)
{
    const float* x   = (const float*)d_in[0];
    // d_in[1], d_in[2] (x1, x2) unused; d_in[3] attn_mask is the fixed causal
    // triu mask, reproduced analytically in-kernel.
    const float* Wk_ = (const float*)d_in[4];
    const float* bk_ = (const float*)d_in[5];
    const float* Wq_ = (const float*)d_in[6];
    const float* bq_ = (const float*)d_in[7];
    const float* Wv_ = (const float*)d_in[8];
    const float* bv_ = (const float*)d_in[9];
    const float* Wp_ = (const float*)d_in[10];
    const float* bp_ = (const float*)d_in[11];

    float* out  = (float*)d_out;
    const size_t out_elems  = (size_t)NB * NT * ND;             // 4,194,304
    const size_t w_elems    = (size_t)NB * NT * NT * NH;        // 67,108,864
    const int write_w = ((size_t)out_size >= out_elems + w_elems) ? 1 : 0;
    float* outW = out + out_elems;

    cudaFuncSetAttribute(stats_k,       cudaFuncAttributeMaxDynamicSharedMemorySize, 66048);
    cudaFuncSetAttribute(scores_tf32_k, cudaFuncAttributeMaxDynamicSharedMemorySize, 77824);
    cudaFuncSetAttribute(qkv_async_k,   cudaFuncAttributeMaxDynamicSharedMemorySize, 61440);
    cudaFuncSetAttribute(proj_async_k,  cudaFuncAttributeMaxDynamicSharedMemorySize, 61440);

    const dim3 blk(256);

    // Pre-round + permute x and weights
    preround_k<<<dim3(((NB * NT * ND) / 4 + 255) / 256, 1, 5), blk>>>(x, Wk_, Wq_, Wv_, Wp_);

    // Fused QKV projections (tf32, cp.async pipeline), one launch
    qkv_async_k<<<dim3(ND / 128, (NB * NT) / 128, 3), blk, 61440>>>(bk_, bq_, bv_);

    // raw scores (masked + scaled), tf32 MMA, per (b,h)
    scores_tf32_k<<<dim3(NT / 128, NT / 128, NB * NH), blk, 77824>>>();

    // per-row softmax stats + weights output
    stats_k<<<NB * NT, dim3(512), 66048>>>(outW, write_w);

    // AV with exp-on-load, tf32 MMA, permuted pre-rounded output
    av_tf32_k<<<dim3(1, NT / 128, NB * NH), blk>>>();

    // output projection (tf32, cp.async pipeline)
    proj_async_k<<<dim3(ND / 128, (NB * NT) / 128), blk, 61440>>>(bp_, out);
}

// round 14
// speedup vs baseline: 1.1054x; 1.1054x over previous
#include <cuda_runtime.h>
#include <cstdint>

// Problem constants
#define NB  4
#define NT  1024
#define ND  1024
#define NH  16
#define NHD 64

// ---------------------------------------------------------------------------
// Scratch (alloc-free: __device__ globals)
// ---------------------------------------------------------------------------
static __device__ float g_K  [(size_t)NB * NT * ND];           // 16 MB (tf32-rounded)
static __device__ float g_Q  [(size_t)NB * NT * ND];           // 16 MB (tf32-rounded)
static __device__ float g_V  [(size_t)NB * NT * ND];           // 16 MB (tf32-rounded)
static __device__ float g_AO [(size_t)NB * NT * ND];           // 16 MB (tf32-rounded)
static __device__ float g_S  [(size_t)NB * NH * NT * NT];      // 256 MB  [b,h,k,q] raw scores
static __device__ float g_stM[(size_t)NB * NH * NT];           // per-row max
static __device__ float g_stI[(size_t)NB * NH * NT];           // per-row 1/sum
static __device__ float g_X  [(size_t)NB * NT * ND];           // 16 MB  rna(x)
static __device__ float g_W4 [(size_t)4  * ND * ND];           // 16 MB  rna(Wk|Wq|Wv|Wp)

// ---------------------------------------------------------------------------
// tf32 / mma helpers
// ---------------------------------------------------------------------------
__device__ __forceinline__ uint32_t f2tf32(float v) {
    uint32_t u;
    asm("cvt.rna.tf32.f32 %0, %1;" : "=r"(u) : "f"(v));
    return u;
}
__device__ __forceinline__ float f2tf32f(float v) { return __uint_as_float(f2tf32(v)); }

__device__ __forceinline__ void mma_tf32(float& c0, float& c1, float& c2, float& c3,
                                         uint32_t a0, uint32_t a1, uint32_t a2, uint32_t a3,
                                         uint32_t b0, uint32_t b1) {
    asm volatile(
        "mma.sync.aligned.m16n8k8.row.col.f32.tf32.tf32.f32 "
        "{%0,%1,%2,%3}, {%4,%5,%6,%7}, {%8,%9}, {%0,%1,%2,%3};"
        : "+f"(c0), "+f"(c1), "+f"(c2), "+f"(c3)
        : "r"(a0), "r"(a1), "r"(a2), "r"(a3), "r"(b0), "r"(b1));
}

// ---------------------------------------------------------------------------
// cp.async helpers
// ---------------------------------------------------------------------------
__device__ __forceinline__ void cp_async16(uint32_t dst, const void* src) {
    asm volatile("cp.async.cg.shared.global [%0], [%1], 16;" :: "r"(dst), "l"(src));
}
__device__ __forceinline__ void cp_commit() {
    asm volatile("cp.async.commit_group;" ::: "memory");
}
__device__ __forceinline__ void cp_wait1() {
    asm volatile("cp.async.wait_group 1;" ::: "memory");
}

// ---------------------------------------------------------------------------
// Pre-round pass: dst[i] = rna_tf32(src[i]) for x and the 4 weight matrices.
// grid.z: 0 = x (1M float4), 1..4 = Wk,Wq,Wv,Wp (256K float4 each).
// ---------------------------------------------------------------------------
__global__ __launch_bounds__(256) void preround_k(
    const float* __restrict__ x,
    const float* __restrict__ Wk, const float* __restrict__ Wq,
    const float* __restrict__ Wv, const float* __restrict__ Wp)
{
    const int z = blockIdx.z;
    const float* src; float* dst; int n4;
    if (z == 0) { src = x;  dst = g_X;               n4 = (NB * NT * ND) / 4; }
    else {
        const float* Ws[4] = {Wk, Wq, Wv, Wp};
        src = Ws[z - 1]; dst = g_W4 + (size_t)(z - 1) * ND * ND; n4 = (ND * ND) / 4;
    }
    const int i = blockIdx.x * 256 + threadIdx.x;
    if (i < n4) {
        float4 v = ((const float4*)src)[i];
        v.x = f2tf32f(v.x); v.y = f2tf32f(v.y);
        v.z = f2tf32f(v.z); v.w = f2tf32f(v.w);
        ((float4*)dst)[i] = v;
    }
}

// ---------------------------------------------------------------------------
// Async-pipelined tf32 GEMM body: C[m,n] = sum_k A[m,k]*W[n,k] + bias[n]
// Inputs MUST be pre-rounded to tf32. 128x128 block, K-step 16, 3-stage
// cp.async pipeline. SMEM row stride 20 words. 8 warps, warp tile 32x64.
// round_c: write C pre-rounded to tf32 (for internal tensors consumed by
// later tf32 MMAs — makes their staging cvt a no-op).
// dynamic smem: 6 * 128 * 20 * 4 = 61440 bytes
// ---------------------------------------------------------------------------
#define PSTG 2560              // floats per stage per matrix (128*20)

__device__ __forceinline__ void gemm_async_body(
    const float* __restrict__ A,
    const float* __restrict__ W,
    const float* __restrict__ bias,
    float* __restrict__ C,
    float* smem, const int round_c)
{
    const int m0 = blockIdx.y * 128, n0 = blockIdx.x * 128;
    const int tid  = threadIdx.x;
    const int wid  = tid >> 5, lane = tid & 31;
    const int gid  = lane >> 2, tg = lane & 3;
    const int wr   = (wid & 3) * 32;
    const int wc   = (wid >> 2) * 64;

    const int lrow = tid >> 2;          // 0..63
    const int lcol = (tid & 3) * 4;     // 0,4,8,12

    const float* Ag0 = A + (size_t)(m0 + lrow) * ND + lcol;
    const float* Ag1 = Ag0 + (size_t)64 * ND;
    const float* Wg0 = W + (size_t)(n0 + lrow) * ND + lcol;
    const float* Wg1 = Wg0 + (size_t)64 * ND;

    const uint32_t sbase = (uint32_t)__cvta_generic_to_shared(smem);
    const uint32_t loff  = (uint32_t)(lrow * 20 + lcol) * 4;
    const uint32_t rstep = 64 * 20 * 4;

    float acc[2][8][4] = {};

    #define ISSUE(k0_, s_)                                                     \
    {                                                                          \
        const uint32_t sa = sbase + (uint32_t)(s_) * PSTG * 4 + loff;          \
        const uint32_t sb = sa + 3 * PSTG * 4;                                 \
        cp_async16(sa,         Ag0 + (k0_));                                   \
        cp_async16(sa + rstep, Ag1 + (k0_));                                   \
        cp_async16(sb,         Wg0 + (k0_));                                   \
        cp_async16(sb + rstep, Wg1 + (k0_));                                   \
    }

    // prologue: stages 0,1
    ISSUE(0, 0)  cp_commit();
    ISSUE(16, 1) cp_commit();

    int slot = 0;
    for (int k0 = 0; k0 < ND; k0 += 16) {
        cp_wait1();
        __syncthreads();

        // issue k0+32 into the slot that held k0-16 (finished last iteration)
        if (k0 + 32 < ND) {
            const int ns = (slot + 2 >= 3) ? slot - 1 : slot + 2;
            ISSUE(k0 + 32, ns)
        }
        cp_commit();

        const float* sAp = smem + slot * PSTG;
        const float* sBp = sAp + 3 * PSTG;

        #pragma unroll
        for (int oct = 0; oct < 2; oct++) {
            const int kc = oct * 8 + tg;
            uint32_t af[2][4], bf[8][2];
            #pragma unroll
            for (int mi = 0; mi < 2; mi++) {
                const int r = wr + mi * 16 + gid;
                af[mi][0] = __float_as_uint(sAp[(r    ) * 20 + kc]);
                af[mi][1] = __float_as_uint(sAp[(r + 8) * 20 + kc]);
                af[mi][2] = __float_as_uint(sAp[(r    ) * 20 + kc + 4]);
                af[mi][3] = __float_as_uint(sAp[(r + 8) * 20 + kc + 4]);
            }
            #pragma unroll
            for (int nj = 0; nj < 8; nj++) {
                const int c = wc + nj * 8 + gid;
                bf[nj][0] = __float_as_uint(sBp[c * 20 + kc]);
                bf[nj][1] = __float_as_uint(sBp[c * 20 + kc + 4]);
            }
            #pragma unroll
            for (int mi = 0; mi < 2; mi++)
                #pragma unroll
                for (int nj = 0; nj < 8; nj++)
                    mma_tf32(acc[mi][nj][0], acc[mi][nj][1], acc[mi][nj][2], acc[mi][nj][3],
                             af[mi][0], af[mi][1], af[mi][2], af[mi][3],
                             bf[nj][0], bf[nj][1]);
        }

        slot = (slot == 2) ? 0 : slot + 1;
    }
    #undef ISSUE

    #pragma unroll
    for (int mi = 0; mi < 2; mi++) {
        #pragma unroll
        for (int nj = 0; nj < 8; nj++) {
            const int gn = n0 + wc + nj * 8 + 2 * tg;
            const float b0v = bias[gn], b1v = bias[gn + 1];
            const int gm0 = m0 + wr + mi * 16 + gid;
            float2 v0; v0.x = acc[mi][nj][0] + b0v; v0.y = acc[mi][nj][1] + b1v;
            float2 v1; v1.x = acc[mi][nj][2] + b0v; v1.y = acc[mi][nj][3] + b1v;
            if (round_c) {
                v0.x = f2tf32f(v0.x); v0.y = f2tf32f(v0.y);
                v1.x = f2tf32f(v1.x); v1.y = f2tf32f(v1.y);
            }
            *(float2*)&C[(size_t)gm0 * ND + gn]       = v0;
            *(float2*)&C[(size_t)(gm0 + 8) * ND + gn] = v1;
        }
    }
}

// Fused QKV: grid.z selects which projection this block computes.
// Outputs are written tf32-rounded (consumed only by tf32 MMAs downstream).
__global__ __launch_bounds__(256, 2) void qkv_async_k(
    const float* __restrict__ bk, const float* __restrict__ bq, const float* __restrict__ bv)
{
    extern __shared__ float smem[];
    const int z = blockIdx.z;
    const float* W = g_W4 + (size_t)z * ND * ND;
    const float* b = (z == 0) ? bk : (z == 1) ? bq : bv;
    float*       C = (z == 0) ? g_K : (z == 1) ? g_Q : g_V;
    gemm_async_body(g_X, W, b, C, smem, 1);
}

__global__ __launch_bounds__(256, 2) void proj_async_k(
    const float* __restrict__ bias,
    float* __restrict__ C)
{
    extern __shared__ float smem[];
    gemm_async_body(g_AO, g_W4 + (size_t)3 * ND * ND, bias, C, smem, 0);
}

// ---------------------------------------------------------------------------
// scores (tf32): scores[b,h,k,q] = (q>k) ? -1e30 : dot(K_row, Q_row) / 32
// 128x128 block per (b,h); K=64 staged once; permuted-k SMEM, stride 76.
// Inputs are pre-rounded tf32 (qkv epilogue) -> staging is a pure copy.
// dynamic smem: 2 * 128 * 76 * 4 = 77824 B
// ---------------------------------------------------------------------------
__global__ __launch_bounds__(256, 2) void scores_tf32_k()
{
    extern __shared__ float sh[];
    float (*As)[76] = (float(*)[76])sh;                // [m][perm-k] K-rows
    float (*Bs)[76] = (float(*)[76])(sh + 128 * 76);   // [n][perm-k] Q-rows

    const int z = blockIdx.z, b = z >> 4, h = z & 15;
    const int m0 = blockIdx.y * 128, n0 = blockIdx.x * 128;  // m=k-idx, n=q-idx
    if (n0 > m0 + 127) return;                               // fully masked tile

    const float* __restrict__ A  = g_K + (size_t)b * NT * ND + h * NHD;
    const float* __restrict__ Bm = g_Q + (size_t)b * NT * ND + h * NHD;
    float* __restrict__ C = g_S + (size_t)z * NT * NT;

    const int tid = threadIdx.x;
    const int wid = tid >> 5, lane = tid & 31;
    const int gid = lane >> 2, tg = lane & 3;
    const int wr  = (wid & 3) * 32;
    const int wc  = (wid >> 2) * 64;

    // Stage full K=64 slab (permuted columns: pair (k, k+4) adjacent)
    #pragma unroll
    for (int i = 0; i < 8; i++) {
        const int idx = tid + i * 256;
        const int row = idx >> 4, c4 = (idx & 15) * 4;       // c4 in {0,4,...,60}
        const int pb  = (c4 & ~7) | ((c4 >> 2) & 1);         // octet base + parity
        float4 a4 = *(const float4*)&A [(size_t)(m0 + row) * ND + c4];
        float4 b4 = *(const float4*)&Bm[(size_t)(n0 + row) * ND + c4];
        As[row][pb+0] = a4.x; As[row][pb+2] = a4.y;
        As[row][pb+4] = a4.z; As[row][pb+6] = a4.w;
        Bs[row][pb+0] = b4.x; Bs[row][pb+2] = b4.y;
        Bs[row][pb+4] = b4.z; Bs[row][pb+6] = b4.w;
    }
    __syncthreads();

    float acc[2][8][4] = {};

    #pragma unroll
    for (int k0 = 0; k0 < NHD; k0 += 8) {
        const int kc = k0 + 2 * tg;
        uint32_t af[2][4], bf[8][2];
        #pragma unroll
        for (int mi = 0; mi < 2; mi++) {
            const int r = wr + mi * 16 + gid;
            float2 f0 = *(const float2*)&As[r    ][kc];
            float2 f1 = *(const float2*)&As[r + 8][kc];
            af[mi][0] = __float_as_uint(f0.x); af[mi][2] = __float_as_uint(f0.y);
            af[mi][1] = __float_as_uint(f1.x); af[mi][3] = __float_as_uint(f1.y);
        }
        #pragma unroll
        for (int nj = 0; nj < 8; nj++) {
            const int c = wc + nj * 8 + gid;
            float2 fb = *(const float2*)&Bs[c][kc];
            bf[nj][0] = __float_as_uint(fb.x); bf[nj][1] = __float_as_uint(fb.y);
        }
        #pragma unroll
        for (int mi = 0; mi < 2; mi++)
            #pragma unroll
            for (int nj = 0; nj < 8; nj++)
                mma_tf32(acc[mi][nj][0], acc[mi][nj][1], acc[mi][nj][2], acc[mi][nj][3],
                         af[mi][0], af[mi][1], af[mi][2], af[mi][3],
                         bf[nj][0], bf[nj][1]);
    }

    #pragma unroll
    for (int mi = 0; mi < 2; mi++) {
        #pragma unroll
        for (int nj = 0; nj < 8; nj++) {
            const int gn  = n0 + wc + nj * 8 + 2 * tg;
            const int gm0 = m0 + wr + mi * 16 + gid;
            float2 v0, v1;
            v0.x = (gn     > gm0)     ? -1e30f : acc[mi][nj][0] * 0.03125f;
            v0.y = (gn + 1 > gm0)     ? -1e30f : acc[mi][nj][1] * 0.03125f;
            v1.x = (gn     > gm0 + 8) ? -1e30f : acc[mi][nj][2] * 0.03125f;
            v1.y = (gn + 1 > gm0 + 8) ? -1e30f : acc[mi][nj][3] * 0.03125f;
            *(float2*)&C[(size_t)gm0 * NT + gn]       = v0;
            *(float2*)&C[(size_t)(gm0 + 8) * NT + gn] = v1;
        }
    }
}

// ---------------------------------------------------------------------------
// Stats + weights output for one (b,k) row-group, 512 threads = 16 warps,
// ONE WARP PER HEAD. All reduction loops bounded by the causal limit kidx
// (everything beyond is -1e30 -> contributes nothing). SMEM beyond kidx is
// never read. Row stride 1032 (16B-aligned rows, conflict-free reduction).
// dynamic smem: 16 * 1032 * 4 = 66048 bytes
// ---------------------------------------------------------------------------
#define SHS 1032

__global__ __launch_bounds__(512) void stats_k(float* __restrict__ outW, int write_w)
{
    extern __shared__ float sh[];           // [16][SHS]
    __shared__ float s_inv[16];
    __shared__ float s_max[16];

    const int bk = blockIdx.x;
    const int b = bk >> 10, kidx = bk & 1023;
    const int tid = threadIdx.x;
    const size_t sbase = (size_t)b * NH * NT * NT + (size_t)kidx * NT;

    const int warp = tid >> 5, lane = tid & 31;

    // Warp `warp` owns head `warp`: fused fill + masked max over q <= kidx
    {
        const int h = warp;
        const float* __restrict__ src = &g_S[sbase + (size_t)h * NT * NT];
        float* __restrict__ dst = &sh[h * SHS];
        const int nq4 = (kidx >> 2) + 1;          // float4 count covering q<=kidx

        float m = -1e30f;
        for (int q4 = lane; q4 < nq4; q4 += 32) {
            const int q = q4 * 4;
            float4 v = *(const float4*)&src[q];
            *(float4*)&dst[q] = v;
            m = fmaxf(m, v.x);                                  // q <= kidx always
            m = fmaxf(m, (q + 1 <= kidx) ? v.y : -1e30f);
            m = fmaxf(m, (q + 2 <= kidx) ? v.z : -1e30f);
            m = fmaxf(m, (q + 3 <= kidx) ? v.w : -1e30f);
        }
        #pragma unroll
        for (int o = 16; o; o >>= 1) m = fmaxf(m, __shfl_xor_sync(0xffffffffu, m, o));

        float s = 0.f;
        for (int q = lane; q <= kidx; q += 32) {
            const float e = __expf(dst[q] - m);
            dst[q] = e;
            s += e;
        }
        #pragma unroll
        for (int o = 16; o; o >>= 1) s += __shfl_xor_sync(0xffffffffu, s, o);
        if (lane == 0) { s_inv[h] = 1.0f / s; s_max[h] = m; }
    }
    __syncthreads();

    if (tid < NH) {
        g_stM[((size_t)b * NH + tid) * NT + kidx] = s_max[tid];
        g_stI[((size_t)b * NH + tid) * NT + kidx] = s_inv[tid];
    }

    if (write_w) {
        float* __restrict__ W = outW + (size_t)bk * NT * NH;
        for (int i = tid; i < (NT * NH) / 4; i += 512) {
            const int base = i * 4;
            const int q = base >> 4, h0 = base & 15;   // 4 consecutive heads, same q
            float4 v;
            if (q <= kidx) {
                v.x = sh[(h0+0) * SHS + q] * s_inv[h0+0];
                v.y = sh[(h0+1) * SHS + q] * s_inv[h0+1];
                v.z = sh[(h0+2) * SHS + q] * s_inv[h0+2];
                v.w = sh[(h0+3) * SHS + q] * s_inv[h0+3];
            } else {
                v.x = v.y = v.z = v.w = 0.f;
            }
            *(float4*)&W[base] = v;
        }
    }
}

// ---------------------------------------------------------------------------
// AV (tf32): AttnOut[b,k,h,:] = sum_q w[b,h,k,q] * V[b,q,h,:]
// Reads RAW scores, applies exp(v-m)*inv during SMEM fill (cvt needed there);
// V is pre-rounded tf32 -> pure copy. Epilogue stores rna_tf32(acc).
// 128(M) x 64(N) block, K-step 32, K truncated at 128-aligned diagonal.
// ---------------------------------------------------------------------------
__global__ __launch_bounds__(256, 2) void av_tf32_k()
{
    __shared__ float As[128][36];   // [m][k] exp-weights (tf32 bits)
    __shared__ float Bs[64][36];    // [n][k] V^T (tf32 bits)
    __shared__ float rm[128], ri[128];

    const int z = blockIdx.z, b = z >> 4, h = z & 15;
    const int m0 = blockIdx.y * 128;
    const float* __restrict__ A  = g_S + (size_t)z * NT * NT;            // raw [k,q]
    const float* __restrict__ Bm = g_V + (size_t)b * NT * ND + h * NHD;  // [q,64] stride ND
    float* __restrict__ C = g_AO + (size_t)b * NT * ND + h * NHD;

    const int tid = threadIdx.x;
    const int wid = tid >> 5, lane = tid & 31;
    const int gid = lane >> 2, tg = lane & 3;
    const int wr  = wid * 16;

    if (tid < 128) {
        rm[tid] = g_stM[(size_t)z * NT + m0 + tid];
        ri[tid] = g_stI[(size_t)z * NT + m0 + tid];
    }
    __syncthreads();

    float acc[8][4] = {};

    const int Kend = m0 + 128;               // causal truncation (128-aligned)
    for (int k0 = 0; k0 < Kend; k0 += 32) {
        #pragma unroll
        for (int i = 0; i < 4; i++) {
            const int idx = tid + i * 256;
            const int row = idx >> 3, c4 = (idx & 7) * 4;
            float4 v = *(const float4*)&A[(size_t)(m0 + row) * NT + k0 + c4];
            const float m = rm[row], inv = ri[row];
            As[row][c4+0] = f2tf32f(__expf(v.x - m) * inv);
            As[row][c4+1] = f2tf32f(__expf(v.y - m) * inv);
            As[row][c4+2] = f2tf32f(__expf(v.z - m) * inv);
            As[row][c4+3] = f2tf32f(__expf(v.w - m) * inv);
        }
        #pragma unroll
        for (int i = 0; i < 2; i++) {
            const int idx = tid + i * 256;
            const int kk = idx >> 4, n4 = (idx & 15) * 4;
            float4 v = *(const float4*)&Bm[(size_t)(k0 + kk) * ND + n4];
            Bs[n4+0][kk] = v.x;
            Bs[n4+1][kk] = v.y;
            Bs[n4+2][kk] = v.z;
            Bs[n4+3][kk] = v.w;
        }
        __syncthreads();

        #pragma unroll
        for (int ks = 0; ks < 32; ks += 8) {
            uint32_t af[4], bf[8][2];
            const int r = wr + gid;
            af[0] = __float_as_uint(As[r    ][ks + tg]);
            af[1] = __float_as_uint(As[r + 8][ks + tg]);
            af[2] = __float_as_uint(As[r    ][ks + tg + 4]);
            af[3] = __float_as_uint(As[r + 8][ks + tg + 4]);
            #pragma unroll
            for (int nj = 0; nj < 8; nj++) {
                const int c = nj * 8 + gid;
                bf[nj][0] = __float_as_uint(Bs[c][ks + tg]);
                bf[nj][1] = __float_as_uint(Bs[c][ks + tg + 4]);
            }
            #pragma unroll
            for (int nj = 0; nj < 8; nj++)
                mma_tf32(acc[nj][0], acc[nj][1], acc[nj][2], acc[nj][3],
                         af[0], af[1], af[2], af[3], bf[nj][0], bf[nj][1]);
        }
        __syncthreads();
    }

    // store pre-rounded to tf32 (exact-RNA input for the final async GEMM)
    #pragma unroll
    for (int nj = 0; nj < 8; nj++) {
        const int gn  = nj * 8 + 2 * tg;
        const int gm0 = m0 + wr + gid;
        float2 v0; v0.x = f2tf32f(acc[nj][0]); v0.y = f2tf32f(acc[nj][1]);
        float2 v1; v1.x = f2tf32f(acc[nj][2]); v1.y = f2tf32f(acc[nj][3]);
        *(float2*)&C[(size_t)gm0 * ND + gn]       = v0;
        *(float2*)&C[(size_t)(gm0 + 8) * ND + gn] = v1;
    }
}

// ---------------------------------------------------------------------------
// Launch
// ---------------------------------------------------------------------------
extern "C" void kernel_launch(void* const* d_in, const int* in_sizes, int n_in,
                              void* d_out, int out_size)
{
    const float* x   = (const float*)d_in[0];
    // d_in[1], d_in[2] (x1, x2) unused; d_in[3] attn_mask is the fixed causal
    // triu mask, reproduced analytically in-kernel.
    const float* Wk_ = (const float*)d_in[4];
    const float* bk_ = (const float*)d_in[5];
    const float* Wq_ = (const float*)d_in[6];
    const float* bq_ = (const float*)d_in[7];
    const float* Wv_ = (const float*)d_in[8];
    const float* bv_ = (const float*)d_in[9];
    const float* Wp_ = (const float*)d_in[10];
    const float* bp_ = (const float*)d_in[11];

    float* out  = (float*)d_out;
    const size_t out_elems  = (size_t)NB * NT * ND;             // 4,194,304
    const size_t w_elems    = (size_t)NB * NT * NT * NH;        // 67,108,864
    const int write_w = ((size_t)out_size >= out_elems + w_elems) ? 1 : 0;
    float* outW = out + out_elems;

    cudaFuncSetAttribute(stats_k,       cudaFuncAttributeMaxDynamicSharedMemorySize, 66048);
    cudaFuncSetAttribute(scores_tf32_k, cudaFuncAttributeMaxDynamicSharedMemorySize, 77824);
    cudaFuncSetAttribute(qkv_async_k,   cudaFuncAttributeMaxDynamicSharedMemorySize, 61440);
    cudaFuncSetAttribute(proj_async_k,  cudaFuncAttributeMaxDynamicSharedMemorySize, 61440);

    const dim3 blk(256);

    // Pre-round x + weights to tf32 (RNA) so async GEMMs get exact numerics
    preround_k<<<dim3(((NB * NT * ND) / 4 + 255) / 256, 1, 5), blk>>>(x, Wk_, Wq_, Wv_, Wp_);

    // Fused QKV projections (tf32, cp.async pipeline), one launch
    qkv_async_k<<<dim3(ND / 128, (NB * NT) / 128, 3), blk, 61440>>>(bk_, bq_, bv_);

    // raw scores (masked + scaled), tf32 MMA, per (b,h)
    scores_tf32_k<<<dim3(NT / 128, NT / 128, NB * NH), blk, 77824>>>();

    // per-row softmax stats + weights output (warp-per-head, causally bounded)
    stats_k<<<NB * NT, dim3(512), 66048>>>(outW, write_w);

    // AV with exp-on-load, tf32 MMA, pre-rounded output
    av_tf32_k<<<dim3(1, NT / 128, NB * NH), blk>>>();

    // output projection (tf32, cp.async pipeline)
    proj_async_k<<<dim3(ND / 128, (NB * NT) / 128), blk, 61440>>>(bp_, out);
}

// round 15
// speedup vs baseline: 1.1170x; 1.0105x over previous
#include <cuda_runtime.h>
#include <cstdint>

// Problem constants
#define NB  4
#define NT  1024
#define ND  1024
#define NH  16
#define NHD 64

// ---------------------------------------------------------------------------
// Scratch (alloc-free: __device__ globals)
// ---------------------------------------------------------------------------
static __device__ float g_K  [(size_t)NB * NT * ND];           // 16 MB (tf32-rounded)
static __device__ float g_Q  [(size_t)NB * NT * ND];           // 16 MB (tf32-rounded)
static __device__ float g_V  [(size_t)NB * NT * ND];           // 16 MB (tf32-rounded)
static __device__ float g_AO [(size_t)NB * NT * ND];           // 16 MB (tf32-rounded)
static __device__ float g_S  [(size_t)NB * NH * NT * NT];      // 256 MB  [b,h,k,q] raw scores
static __device__ float g_stM[(size_t)NB * NH * NT];           // per-row max
static __device__ float g_stI[(size_t)NB * NH * NT];           // per-row 1/sum
static __device__ float g_X  [(size_t)NB * NT * ND];           // 16 MB  rna(x)
static __device__ float g_W4 [(size_t)4  * ND * ND];           // 16 MB  rna(Wk|Wq|Wv|Wp)

// ---------------------------------------------------------------------------
// tf32 / mma helpers
// ---------------------------------------------------------------------------
__device__ __forceinline__ uint32_t f2tf32(float v) {
    uint32_t u;
    asm("cvt.rna.tf32.f32 %0, %1;" : "=r"(u) : "f"(v));
    return u;
}
__device__ __forceinline__ float f2tf32f(float v) { return __uint_as_float(f2tf32(v)); }

__device__ __forceinline__ void mma_tf32(float& c0, float& c1, float& c2, float& c3,
                                         uint32_t a0, uint32_t a1, uint32_t a2, uint32_t a3,
                                         uint32_t b0, uint32_t b1) {
    asm volatile(
        "mma.sync.aligned.m16n8k8.row.col.f32.tf32.tf32.f32 "
        "{%0,%1,%2,%3}, {%4,%5,%6,%7}, {%8,%9}, {%0,%1,%2,%3};"
        : "+f"(c0), "+f"(c1), "+f"(c2), "+f"(c3)
        : "r"(a0), "r"(a1), "r"(a2), "r"(a3), "r"(b0), "r"(b1));
}

// ---------------------------------------------------------------------------
// cp.async helpers
// ---------------------------------------------------------------------------
__device__ __forceinline__ void cp_async16(uint32_t dst, const void* src) {
    asm volatile("cp.async.cg.shared.global [%0], [%1], 16;" :: "r"(dst), "l"(src));
}
__device__ __forceinline__ void cp_commit() {
    asm volatile("cp.async.commit_group;" ::: "memory");
}
__device__ __forceinline__ void cp_wait1() {
    asm volatile("cp.async.wait_group 1;" ::: "memory");
}

// ---------------------------------------------------------------------------
// Pre-round pass: dst[i] = rna_tf32(src[i]) for x and the 4 weight matrices.
// grid.z: 0 = x (1M float4), 1..4 = Wk,Wq,Wv,Wp (256K float4 each).
// ---------------------------------------------------------------------------
__global__ __launch_bounds__(256) void preround_k(
    const float* __restrict__ x,
    const float* __restrict__ Wk, const float* __restrict__ Wq,
    const float* __restrict__ Wv, const float* __restrict__ Wp)
{
    const int z = blockIdx.z;
    const float* src; float* dst; int n4;
    if (z == 0) { src = x;  dst = g_X;               n4 = (NB * NT * ND) / 4; }
    else {
        const float* Ws[4] = {Wk, Wq, Wv, Wp};
        src = Ws[z - 1]; dst = g_W4 + (size_t)(z - 1) * ND * ND; n4 = (ND * ND) / 4;
    }
    const int i = blockIdx.x * 256 + threadIdx.x;
    if (i < n4) {
        float4 v = ((const float4*)src)[i];
        v.x = f2tf32f(v.x); v.y = f2tf32f(v.y);
        v.z = f2tf32f(v.z); v.w = f2tf32f(v.w);
        ((float4*)dst)[i] = v;
    }
}

// ---------------------------------------------------------------------------
// Async-pipelined tf32 GEMM body: C[m,n] = sum_k A[m,k]*W[n,k] + bias[n]
// Inputs MUST be pre-rounded to tf32.
// 256(M) x 128(N) block, K-step 16, 3-stage cp.async pipeline, 8 warps,
// warp tile 64x64 (mi=4, nj=8) -> 16.4 FLOP per SMEM byte (crossbar-balanced).
// SMEM row stride 20 words. 1 CTA/SM (128 acc regs/thread).
// Stage: A 256x20 + B 128x20 = 7680 floats (30720 B); 3 stages = 92160 B.
// ---------------------------------------------------------------------------
#define STGF 7680              // floats per stage (A 5120 + B 2560)
#define BOFF 5120              // B offset within a stage (floats)

__device__ __forceinline__ void gemm_async_body(
    const float* __restrict__ A,
    const float* __restrict__ W,
    const float* __restrict__ bias,
    float* __restrict__ C,
    float* smem, const int round_c)
{
    const int m0 = blockIdx.y * 256, n0 = blockIdx.x * 128;
    const int tid  = threadIdx.x;
    const int wid  = tid >> 5, lane = tid & 31;
    const int gid  = lane >> 2, tg = lane & 3;
    const int wr   = (wid & 3) * 64;      // 4 warps over M
    const int wc   = (wid >> 2) * 64;     // 2 warps over N

    const int lrow = tid >> 2;          // 0..63
    const int lcol = (tid & 3) * 4;     // 0,4,8,12

    const float* Ag = A + (size_t)(m0 + lrow) * ND + lcol;
    const float* Wg = W + (size_t)(n0 + lrow) * ND + lcol;

    const uint32_t sbase = (uint32_t)__cvta_generic_to_shared(smem);
    const uint32_t loff  = (uint32_t)(lrow * 20 + lcol) * 4;
    const uint32_t rstep = 64 * 20 * 4;   // 64 rows of SMEM

    float acc[4][8][4] = {};

    #define ISSUE(k0_, s_)                                                     \
    {                                                                          \
        const uint32_t sa = sbase + (uint32_t)(s_) * STGF * 4 + loff;          \
        const uint32_t sb = sa + BOFF * 4;                                     \
        cp_async16(sa,             Ag + (k0_));                                \
        cp_async16(sa +     rstep, Ag + (k0_) + (size_t)64  * ND);             \
        cp_async16(sa + 2 * rstep, Ag + (k0_) + (size_t)128 * ND);             \
        cp_async16(sa + 3 * rstep, Ag + (k0_) + (size_t)192 * ND);             \
        cp_async16(sb,             Wg + (k0_));                                \
        cp_async16(sb +     rstep, Wg + (k0_) + (size_t)64  * ND);             \
    }

    // prologue: stages 0,1
    ISSUE(0, 0)  cp_commit();
    ISSUE(16, 1) cp_commit();

    int slot = 0;
    for (int k0 = 0; k0 < ND; k0 += 16) {
        cp_wait1();
        __syncthreads();

        // issue k0+32 into the slot that held k0-16 (finished last iteration)
        if (k0 + 32 < ND) {
            const int ns = (slot + 2 >= 3) ? slot - 1 : slot + 2;
            ISSUE(k0 + 32, ns)
        }
        cp_commit();

        const float* sAp = smem + slot * STGF;
        const float* sBp = sAp + BOFF;

        #pragma unroll
        for (int oct = 0; oct < 2; oct++) {
            const int kc = oct * 8 + tg;
            uint32_t af[4][4], bf[8][2];
            #pragma unroll
            for (int mi = 0; mi < 4; mi++) {
                const int r = wr + mi * 16 + gid;
                af[mi][0] = __float_as_uint(sAp[(r    ) * 20 + kc]);
                af[mi][1] = __float_as_uint(sAp[(r + 8) * 20 + kc]);
                af[mi][2] = __float_as_uint(sAp[(r    ) * 20 + kc + 4]);
                af[mi][3] = __float_as_uint(sAp[(r + 8) * 20 + kc + 4]);
            }
            #pragma unroll
            for (int nj = 0; nj < 8; nj++) {
                const int c = wc + nj * 8 + gid;
                bf[nj][0] = __float_as_uint(sBp[c * 20 + kc]);
                bf[nj][1] = __float_as_uint(sBp[c * 20 + kc + 4]);
            }
            #pragma unroll
            for (int mi = 0; mi < 4; mi++)
                #pragma unroll
                for (int nj = 0; nj < 8; nj++)
                    mma_tf32(acc[mi][nj][0], acc[mi][nj][1], acc[mi][nj][2], acc[mi][nj][3],
                             af[mi][0], af[mi][1], af[mi][2], af[mi][3],
                             bf[nj][0], bf[nj][1]);
        }

        slot = (slot == 2) ? 0 : slot + 1;
    }
    #undef ISSUE

    #pragma unroll
    for (int mi = 0; mi < 4; mi++) {
        #pragma unroll
        for (int nj = 0; nj < 8; nj++) {
            const int gn = n0 + wc + nj * 8 + 2 * tg;
            const float b0v = bias[gn], b1v = bias[gn + 1];
            const int gm0 = m0 + wr + mi * 16 + gid;
            float2 v0; v0.x = acc[mi][nj][0] + b0v; v0.y = acc[mi][nj][1] + b1v;
            float2 v1; v1.x = acc[mi][nj][2] + b0v; v1.y = acc[mi][nj][3] + b1v;
            if (round_c) {
                v0.x = f2tf32f(v0.x); v0.y = f2tf32f(v0.y);
                v1.x = f2tf32f(v1.x); v1.y = f2tf32f(v1.y);
            }
            *(float2*)&C[(size_t)gm0 * ND + gn]       = v0;
            *(float2*)&C[(size_t)(gm0 + 8) * ND + gn] = v1;
        }
    }
}

// Fused QKV: grid.z selects which projection this block computes.
// Outputs are written tf32-rounded (consumed only by tf32 MMAs downstream).
__global__ __launch_bounds__(256, 1) void qkv_async_k(
    const float* __restrict__ bk, const float* __restrict__ bq, const float* __restrict__ bv)
{
    extern __shared__ float smem[];
    const int z = blockIdx.z;
    const float* W = g_W4 + (size_t)z * ND * ND;
    const float* b = (z == 0) ? bk : (z == 1) ? bq : bv;
    float*       C = (z == 0) ? g_K : (z == 1) ? g_Q : g_V;
    gemm_async_body(g_X, W, b, C, smem, 1);
}

__global__ __launch_bounds__(256, 1) void proj_async_k(
    const float* __restrict__ bias,
    float* __restrict__ C)
{
    extern __shared__ float smem[];
    gemm_async_body(g_AO, g_W4 + (size_t)3 * ND * ND, bias, C, smem, 0);
}

// ---------------------------------------------------------------------------
// scores (tf32): scores[b,h,k,q] = (q>k) ? -1e30 : dot(K_row, Q_row) / 32
// 128x128 block per (b,h); K=64 staged once; permuted-k SMEM, stride 76.
// Inputs are pre-rounded tf32 (qkv epilogue) -> staging is a pure copy.
// dynamic smem: 2 * 128 * 76 * 4 = 77824 B
// ---------------------------------------------------------------------------
__global__ __launch_bounds__(256, 2) void scores_tf32_k()
{
    extern __shared__ float sh[];
    float (*As)[76] = (float(*)[76])sh;                // [m][perm-k] K-rows
    float (*Bs)[76] = (float(*)[76])(sh + 128 * 76);   // [n][perm-k] Q-rows

    const int z = blockIdx.z, b = z >> 4, h = z & 15;
    const int m0 = blockIdx.y * 128, n0 = blockIdx.x * 128;  // m=k-idx, n=q-idx
    if (n0 > m0 + 127) return;                               // fully masked tile

    const float* __restrict__ A  = g_K + (size_t)b * NT * ND + h * NHD;
    const float* __restrict__ Bm = g_Q + (size_t)b * NT * ND + h * NHD;
    float* __restrict__ C = g_S + (size_t)z * NT * NT;

    const int tid = threadIdx.x;
    const int wid = tid >> 5, lane = tid & 31;
    const int gid = lane >> 2, tg = lane & 3;
    const int wr  = (wid & 3) * 32;
    const int wc  = (wid >> 2) * 64;

    // Stage full K=64 slab (permuted columns: pair (k, k+4) adjacent)
    #pragma unroll
    for (int i = 0; i < 8; i++) {
        const int idx = tid + i * 256;
        const int row = idx >> 4, c4 = (idx & 15) * 4;       // c4 in {0,4,...,60}
        const int pb  = (c4 & ~7) | ((c4 >> 2) & 1);         // octet base + parity
        float4 a4 = *(const float4*)&A [(size_t)(m0 + row) * ND + c4];
        float4 b4 = *(const float4*)&Bm[(size_t)(n0 + row) * ND + c4];
        As[row][pb+0] = a4.x; As[row][pb+2] = a4.y;
        As[row][pb+4] = a4.z; As[row][pb+6] = a4.w;
        Bs[row][pb+0] = b4.x; Bs[row][pb+2] = b4.y;
        Bs[row][pb+4] = b4.z; Bs[row][pb+6] = b4.w;
    }
    __syncthreads();

    float acc[2][8][4] = {};

    #pragma unroll
    for (int k0 = 0; k0 < NHD; k0 += 8) {
        const int kc = k0 + 2 * tg;
        uint32_t af[2][4], bf[8][2];
        #pragma unroll
        for (int mi = 0; mi < 2; mi++) {
            const int r = wr + mi * 16 + gid;
            float2 f0 = *(const float2*)&As[r    ][kc];
            float2 f1 = *(const float2*)&As[r + 8][kc];
            af[mi][0] = __float_as_uint(f0.x); af[mi][2] = __float_as_uint(f0.y);
            af[mi][1] = __float_as_uint(f1.x); af[mi][3] = __float_as_uint(f1.y);
        }
        #pragma unroll
        for (int nj = 0; nj < 8; nj++) {
            const int c = wc + nj * 8 + gid;
            float2 fb = *(const float2*)&Bs[c][kc];
            bf[nj][0] = __float_as_uint(fb.x); bf[nj][1] = __float_as_uint(fb.y);
        }
        #pragma unroll
        for (int mi = 0; mi < 2; mi++)
            #pragma unroll
            for (int nj = 0; nj < 8; nj++)
                mma_tf32(acc[mi][nj][0], acc[mi][nj][1], acc[mi][nj][2], acc[mi][nj][3],
                         af[mi][0], af[mi][1], af[mi][2], af[mi][3],
                         bf[nj][0], bf[nj][1]);
    }

    #pragma unroll
    for (int mi = 0; mi < 2; mi++) {
        #pragma unroll
        for (int nj = 0; nj < 8; nj++) {
            const int gn  = n0 + wc + nj * 8 + 2 * tg;
            const int gm0 = m0 + wr + mi * 16 + gid;
            float2 v0, v1;
            v0.x = (gn     > gm0)     ? -1e30f : acc[mi][nj][0] * 0.03125f;
            v0.y = (gn + 1 > gm0)     ? -1e30f : acc[mi][nj][1] * 0.03125f;
            v1.x = (gn     > gm0 + 8) ? -1e30f : acc[mi][nj][2] * 0.03125f;
            v1.y = (gn + 1 > gm0 + 8) ? -1e30f : acc[mi][nj][3] * 0.03125f;
            *(float2*)&C[(size_t)gm0 * NT + gn]       = v0;
            *(float2*)&C[(size_t)(gm0 + 8) * NT + gn] = v1;
        }
    }
}

// ---------------------------------------------------------------------------
// Stats + weights output for one (b,k) row-group, 512 threads = 16 warps,
// ONE WARP PER HEAD. All reduction loops bounded by the causal limit kidx.
// Row stride 1032 (16B-aligned rows, conflict-free reduction).
// dynamic smem: 16 * 1032 * 4 = 66048 bytes
// ---------------------------------------------------------------------------
#define SHS 1032

__global__ __launch_bounds__(512) void stats_k(float* __restrict__ outW, int write_w)
{
    extern __shared__ float sh[];           // [16][SHS]
    __shared__ float s_inv[16];
    __shared__ float s_max[16];

    const int bk = blockIdx.x;
    const int b = bk >> 10, kidx = bk & 1023;
    const int tid = threadIdx.x;
    const size_t sbase = (size_t)b * NH * NT * NT + (size_t)kidx * NT;

    const int warp = tid >> 5, lane = tid & 31;

    // Warp `warp` owns head `warp`: fused fill + masked max over q <= kidx
    {
        const int h = warp;
        const float* __restrict__ src = &g_S[sbase + (size_t)h * NT * NT];
        float* __restrict__ dst = &sh[h * SHS];
        const int nq4 = (kidx >> 2) + 1;          // float4 count covering q<=kidx

        float m = -1e30f;
        for (int q4 = lane; q4 < nq4; q4 += 32) {
            const int q = q4 * 4;
            float4 v = *(const float4*)&src[q];
            *(float4*)&dst[q] = v;
            m = fmaxf(m, v.x);                                  // q <= kidx always
            m = fmaxf(m, (q + 1 <= kidx) ? v.y : -1e30f);
            m = fmaxf(m, (q + 2 <= kidx) ? v.z : -1e30f);
            m = fmaxf(m, (q + 3 <= kidx) ? v.w : -1e30f);
        }
        #pragma unroll
        for (int o = 16; o; o >>= 1) m = fmaxf(m, __shfl_xor_sync(0xffffffffu, m, o));

        float s = 0.f;
        for (int q = lane; q <= kidx; q += 32) {
            const float e = __expf(dst[q] - m);
            dst[q] = e;
            s += e;
        }
        #pragma unroll
        for (int o = 16; o; o >>= 1) s += __shfl_xor_sync(0xffffffffu, s, o);
        if (lane == 0) { s_inv[h] = 1.0f / s; s_max[h] = m; }
    }
    __syncthreads();

    if (tid < NH) {
        g_stM[((size_t)b * NH + tid) * NT + kidx] = s_max[tid];
        g_stI[((size_t)b * NH + tid) * NT + kidx] = s_inv[tid];
    }

    if (write_w) {
        float* __restrict__ W = outW + (size_t)bk * NT * NH;
        for (int i = tid; i < (NT * NH) / 4; i += 512) {
            const int base = i * 4;
            const int q = base >> 4, h0 = base & 15;   // 4 consecutive heads, same q
            float4 v;
            if (q <= kidx) {
                v.x = sh[(h0+0) * SHS + q] * s_inv[h0+0];
                v.y = sh[(h0+1) * SHS + q] * s_inv[h0+1];
                v.z = sh[(h0+2) * SHS + q] * s_inv[h0+2];
                v.w = sh[(h0+3) * SHS + q] * s_inv[h0+3];
            } else {
                v.x = v.y = v.z = v.w = 0.f;
            }
            *(float4*)&W[base] = v;
        }
    }
}

// ---------------------------------------------------------------------------
// AV (tf32): AttnOut[b,k,h,:] = sum_q w[b,h,k,q] * V[b,q,h,:]
// Reads RAW scores, applies exp(v-m)*inv during SMEM fill (cvt needed there);
// V is pre-rounded tf32 -> pure copy. Epilogue stores rna_tf32(acc).
// 128(M) x 64(N) block, K-step 32, K truncated at 128-aligned diagonal.
// ---------------------------------------------------------------------------
__global__ __launch_bounds__(256, 2) void av_tf32_k()
{
    __shared__ float As[128][36];   // [m][k] exp-weights (tf32 bits)
    __shared__ float Bs[64][36];    // [n][k] V^T (tf32 bits)
    __shared__ float rm[128], ri[128];

    const int z = blockIdx.z, b = z >> 4, h = z & 15;
    const int m0 = blockIdx.y * 128;
    const float* __restrict__ A  = g_S + (size_t)z * NT * NT;            // raw [k,q]
    const float* __restrict__ Bm = g_V + (size_t)b * NT * ND + h * NHD;  // [q,64] stride ND
    float* __restrict__ C = g_AO + (size_t)b * NT * ND + h * NHD;

    const int tid = threadIdx.x;
    const int wid = tid >> 5, lane = tid & 31;
    const int gid = lane >> 2, tg = lane & 3;
    const int wr  = wid * 16;

    if (tid < 128) {
        rm[tid] = g_stM[(size_t)z * NT + m0 + tid];
        ri[tid] = g_stI[(size_t)z * NT + m0 + tid];
    }
    __syncthreads();

    float acc[8][4] = {};

    const int Kend = m0 + 128;               // causal truncation (128-aligned)
    for (int k0 = 0; k0 < Kend; k0 += 32) {
        #pragma unroll
        for (int i = 0; i < 4; i++) {
            const int idx = tid + i * 256;
            const int row = idx >> 3, c4 = (idx & 7) * 4;
            float4 v = *(const float4*)&A[(size_t)(m0 + row) * NT + k0 + c4];
            const float m = rm[row], inv = ri[row];
            As[row][c4+0] = f2tf32f(__expf(v.x - m) * inv);
            As[row][c4+1] = f2tf32f(__expf(v.y - m) * inv);
            As[row][c4+2] = f2tf32f(__expf(v.z - m) * inv);
            As[row][c4+3] = f2tf32f(__expf(v.w - m) * inv);
        }
        #pragma unroll
        for (int i = 0; i < 2; i++) {
            const int idx = tid + i * 256;
            const int kk = idx >> 4, n4 = (idx & 15) * 4;
            float4 v = *(const float4*)&Bm[(size_t)(k0 + kk) * ND + n4];
            Bs[n4+0][kk] = v.x;
            Bs[n4+1][kk] = v.y;
            Bs[n4+2][kk] = v.z;
            Bs[n4+3][kk] = v.w;
        }
        __syncthreads();

        #pragma unroll
        for (int ks = 0; ks < 32; ks += 8) {
            uint32_t af[4], bf[8][2];
            const int r = wr + gid;
            af[0] = __float_as_uint(As[r    ][ks + tg]);
            af[1] = __float_as_uint(As[r + 8][ks + tg]);
            af[2] = __float_as_uint(As[r    ][ks + tg + 4]);
            af[3] = __float_as_uint(As[r + 8][ks + tg + 4]);
            #pragma unroll
            for (int nj = 0; nj < 8; nj++) {
                const int c = nj * 8 + gid;
                bf[nj][0] = __float_as_uint(Bs[c][ks + tg]);
                bf[nj][1] = __float_as_uint(Bs[c][ks + tg + 4]);
            }
            #pragma unroll
            for (int nj = 0; nj < 8; nj++)
                mma_tf32(acc[nj][0], acc[nj][1], acc[nj][2], acc[nj][3],
                         af[0], af[1], af[2], af[3], bf[nj][0], bf[nj][1]);
        }
        __syncthreads();
    }

    // store pre-rounded to tf32 (exact-RNA input for the final async GEMM)
    #pragma unroll
    for (int nj = 0; nj < 8; nj++) {
        const int gn  = nj * 8 + 2 * tg;
        const int gm0 = m0 + wr + gid;
        float2 v0; v0.x = f2tf32f(acc[nj][0]); v0.y = f2tf32f(acc[nj][1]);
        float2 v1; v1.x = f2tf32f(acc[nj][2]); v1.y = f2tf32f(acc[nj][3]);
        *(float2*)&C[(size_t)gm0 * ND + gn]       = v0;
        *(float2*)&C[(size_t)(gm0 + 8) * ND + gn] = v1;
    }
}

// ---------------------------------------------------------------------------
// Launch
// ---------------------------------------------------------------------------
extern "C" void kernel_launch(void* const* d_in, const int* in_sizes, int n_in,
                              void* d_out, int out_size)
{
    const float* x   = (const float*)d_in[0];
    // d_in[1], d_in[2] (x1, x2) unused; d_in[3] attn_mask is the fixed causal
    // triu mask, reproduced analytically in-kernel.
    const float* Wk_ = (const float*)d_in[4];
    const float* bk_ = (const float*)d_in[5];
    const float* Wq_ = (const float*)d_in[6];
    const float* bq_ = (const float*)d_in[7];
    const float* Wv_ = (const float*)d_in[8];
    const float* bv_ = (const float*)d_in[9];
    const float* Wp_ = (const float*)d_in[10];
    const float* bp_ = (const float*)d_in[11];

    float* out  = (float*)d_out;
    const size_t out_elems  = (size_t)NB * NT * ND;             // 4,194,304
    const size_t w_elems    = (size_t)NB * NT * NT * NH;        // 67,108,864
    const int write_w = ((size_t)out_size >= out_elems + w_elems) ? 1 : 0;
    float* outW = out + out_elems;

    cudaFuncSetAttribute(stats_k,       cudaFuncAttributeMaxDynamicSharedMemorySize, 66048);
    cudaFuncSetAttribute(scores_tf32_k, cudaFuncAttributeMaxDynamicSharedMemorySize, 77824);
    cudaFuncSetAttribute(qkv_async_k,   cudaFuncAttributeMaxDynamicSharedMemorySize, 92160);
    cudaFuncSetAttribute(proj_async_k,  cudaFuncAttributeMaxDynamicSharedMemorySize, 92160);

    const dim3 blk(256);

    // Pre-round x + weights to tf32 (RNA) so async GEMMs get exact numerics
    preround_k<<<dim3(((NB * NT * ND) / 4 + 255) / 256, 1, 5), blk>>>(x, Wk_, Wq_, Wv_, Wp_);

    // Fused QKV projections (tf32, cp.async pipeline, 256x128 blocks)
    qkv_async_k<<<dim3(ND / 128, (NB * NT) / 256, 3), blk, 92160>>>(bk_, bq_, bv_);

    // raw scores (masked + scaled), tf32 MMA, per (b,h)
    scores_tf32_k<<<dim3(NT / 128, NT / 128, NB * NH), blk, 77824>>>();

    // per-row softmax stats + weights output (warp-per-head, causally bounded)
    stats_k<<<NB * NT, dim3(512), 66048>>>(outW, write_w);

    // AV with exp-on-load, tf32 MMA, pre-rounded output
    av_tf32_k<<<dim3(1, NT / 128, NB * NH), blk>>>();

    // output projection (tf32, cp.async pipeline, 256x128 blocks)
    proj_async_k<<<dim3(ND / 128, (NB * NT) / 256), blk, 92160>>>(bp_, out);
}